// round 15
// baseline (speedup 1.0000x reference)
#include <cuda_runtime.h>
#include <math.h>
#include <stdint.h>

#define BB   8
#define TT   1024
#define EE   1024
#define HH   16
#define HDD  64
#define MM   (BB*TT)      // 8192 rows
#define LOG2E 1.4426950408889634f

// ---------------------------------------------------------------------------
// Scratch (device globals — allocation-free rule)
// ---------------------------------------------------------------------------
__device__ float g_q[(size_t)BB*TT*EE];
__device__ float g_k[(size_t)BB*TT*EE];
__device__ float g_v[(size_t)BB*TT*EE];
__device__ float g_attn[(size_t)BB*TT*EE];

// ---------------------------------------------------------------------------
// helpers
// ---------------------------------------------------------------------------
__device__ __forceinline__ uint32_t smem_u32(const void* p) {
    uint32_t a;
    asm("{ .reg .u64 t; cvta.to.shared.u64 t, %1; cvt.u32.u64 %0, t; }" : "=r"(a) : "l"(p));
    return a;
}
__device__ __forceinline__ uint32_t f2tf32(float x) {
    uint32_t r; asm("cvt.rna.tf32.f32 %0, %1;" : "=r"(r) : "f"(x)); return r;
}
__device__ __forceinline__ float fexp2(float x) {
    float y; asm("ex2.approx.ftz.f32 %0, %1;" : "=f"(y) : "f"(x)); return y;
}
__device__ __forceinline__ void cp_async16(uint32_t dst, const void* src) {
    asm volatile("cp.async.cg.shared.global [%0], [%1], 16;" :: "r"(dst), "l"(src) : "memory");
}
__device__ __forceinline__ void cp_commit() {
    asm volatile("cp.async.commit_group;" ::: "memory");
}
__device__ __forceinline__ void cp_wait1() {
    asm volatile("cp.async.wait_group 1;" ::: "memory");
}
__device__ __forceinline__ void cp_wait0() {
    asm volatile("cp.async.wait_group 0;" ::: "memory");
}
__device__ __forceinline__ void mma_tf32(float& d0, float& d1, float& d2, float& d3,
                                         uint32_t a0, uint32_t a1, uint32_t a2, uint32_t a3,
                                         uint32_t b0, uint32_t b1) {
    asm volatile(
        "mma.sync.aligned.m16n8k8.row.col.f32.tf32.tf32.f32 "
        "{%0,%1,%2,%3}, {%4,%5,%6,%7}, {%8,%9}, {%0,%1,%2,%3};"
        : "+f"(d0), "+f"(d1), "+f"(d2), "+f"(d3)
        : "r"(a0), "r"(a1), "r"(a2), "r"(a3), "r"(b0), "r"(b1));
}

// ---------------------------------------------------------------------------
// tf32 mma.sync multiway GEMM (unchanged from R13, proven)
// ---------------------------------------------------------------------------
#define ASTRIDE    36
#define TILE_FL    (128 * ASTRIDE)
#define GEMM_SMEM  (2 * 2 * TILE_FL * 4)

__global__ void __launch_bounds__(256, 2) mw_gemm_mma(
    const float* __restrict__ X,
    const float* __restrict__ Wt, const float* __restrict__ bt,
    const float* __restrict__ Wi, const float* __restrict__ bi,
    float* __restrict__ C, float alpha, const int* __restrict__ split_ptr)
{
    extern __shared__ float smf[];
    const int tid  = threadIdx.x;
    const int wid  = tid >> 5;
    const int lane = tid & 31;
    const int g    = lane >> 2;
    const int c    = lane & 3;
    const int warp_m = wid >> 2;
    const int warp_n = wid & 3;

    const int split  = *split_ptr;
    const int tilesT = (BB * split) >> 7;
    const bool isText = (int)blockIdx.y < tilesT;
    const float* __restrict__ W    = isText ? Wt : Wi;
    const float* __restrict__ bias = isText ? bt : bi;
    const int col0 = blockIdx.x * 128;
    const int span = isText ? split : (TT - split);
    const int tokb = isText ? 0 : split;
    const int tloc = isText ? (int)blockIdx.y : (int)blockIdx.y - tilesT;

    const uint32_t sbase = smem_u32(smf);

    const int v4 = (tid & 7) * 4;
    const float* Ap[4];
    const float* Bp[4];
    uint32_t dA[4], dB[4];
#pragma unroll
    for (int j = 0; j < 4; j++) {
        const int r  = (tid >> 3) + j * 32;
        const int gi = tloc * 128 + r;
        const size_t grow = (size_t)(gi / span) * TT + tokb + (gi % span);
        Ap[j] = X + grow * EE + v4;
        Bp[j] = W + (size_t)(col0 + r) * EE + v4;
        dA[j] = sbase + (uint32_t)(r * ASTRIDE * 4 + (tid & 7) * 16);
        dB[j] = dA[j] + TILE_FL * 4;
    }

    float acc[4][4][4];
#pragma unroll
    for (int mt = 0; mt < 4; mt++)
#pragma unroll
        for (int nt = 0; nt < 4; nt++)
#pragma unroll
            for (int e = 0; e < 4; e++) acc[mt][nt][e] = 0.0f;

    const uint32_t stageBytes = 2 * TILE_FL * 4;
#define ISSUE(kt) do {                                                     \
        const uint32_t so = ((kt) & 1) * stageBytes;                       \
        const int ko = (kt) * 32;                                          \
        _Pragma("unroll")                                                  \
        for (int j = 0; j < 4; j++) {                                      \
            cp_async16(dA[j] + so, Ap[j] + ko);                            \
            cp_async16(dB[j] + so, Bp[j] + ko);                            \
        }                                                                  \
        cp_commit();                                                       \
    } while (0)

    ISSUE(0);

    for (int kt = 0; kt < 32; kt++) {
        if (kt + 1 < 32) { ISSUE(kt + 1); cp_wait1(); }
        else             { cp_wait0(); }
        __syncthreads();

        const float* As = smf + (kt & 1) * (2 * TILE_FL);
        const float* Bs = As + TILE_FL;

#pragma unroll
        for (int ks = 0; ks < 4; ks++) {
            uint32_t af[4][4];
#pragma unroll
            for (int mt = 0; mt < 4; mt++) {
                const int row = warp_m * 64 + mt * 16 + g;
                const int col = ks * 8 + c;
                af[mt][0] = f2tf32(As[row * ASTRIDE + col]);
                af[mt][1] = f2tf32(As[(row + 8) * ASTRIDE + col]);
                af[mt][2] = f2tf32(As[row * ASTRIDE + col + 4]);
                af[mt][3] = f2tf32(As[(row + 8) * ASTRIDE + col + 4]);
            }
            uint32_t bf[4][2];
#pragma unroll
            for (int nt = 0; nt < 4; nt++) {
                const int n = warp_n * 32 + nt * 8 + g;
                bf[nt][0] = f2tf32(Bs[n * ASTRIDE + ks * 8 + c]);
                bf[nt][1] = f2tf32(Bs[n * ASTRIDE + ks * 8 + c + 4]);
            }
#pragma unroll
            for (int mt = 0; mt < 4; mt++)
#pragma unroll
                for (int nt = 0; nt < 4; nt++)
                    mma_tf32(acc[mt][nt][0], acc[mt][nt][1], acc[mt][nt][2], acc[mt][nt][3],
                             af[mt][0], af[mt][1], af[mt][2], af[mt][3],
                             bf[nt][0], bf[nt][1]);
        }
        __syncthreads();
    }

#pragma unroll
    for (int mt = 0; mt < 4; mt++) {
        const int r0 = warp_m * 64 + mt * 16 + g;
#pragma unroll
        for (int half = 0; half < 2; half++) {
            const int r  = r0 + half * 8;
            const int gi = tloc * 128 + r;
            const size_t grow = (size_t)(gi / span) * TT + tokb + (gi % span);
            float* __restrict__ Crow = C + grow * EE;
#pragma unroll
            for (int nt = 0; nt < 4; nt++) {
                const int col = col0 + warp_n * 32 + nt * 8 + c * 2;
                float2 o;
                o.x = (acc[mt][nt][half * 2 + 0] + bias[col])     * alpha;
                o.y = (acc[mt][nt][half * 2 + 1] + bias[col + 1]) * alpha;
                *(float2*)(Crow + col) = o;
            }
        }
    }
#undef ISSUE
}

// ---------------------------------------------------------------------------
// tf32 mma.sync flash attention.
//   Block = 128 thr (4 warps), 64 Q-rows/block, S in 64-wide tiles.
//   Warp w owns Q rows w*16..+15. Smem tiles (tf32 bits, stride 68):
//     Qs[r][d], Ks[s][d], Vt[d][s ^ (d&60)], Ps[r][s] (warp-local bounce).
// ---------------------------------------------------------------------------
#define AS 68
#define ATTN_SMEM (4 * 64 * AS * 4)   // 69632 B

__global__ void __launch_bounds__(128) attention_mma(
    const float* __restrict__ q, const float* __restrict__ k,
    const float* __restrict__ v, const float* __restrict__ mask,
    float* __restrict__ out)
{
    extern __shared__ uint32_t smu[];
    uint32_t* Qs = smu;
    uint32_t* Ks = smu + 64 * AS;
    uint32_t* Vt = smu + 2 * 64 * AS;
    uint32_t* Ps = smu + 3 * 64 * AS;

    const int tid  = threadIdx.x;
    const int wid  = tid >> 5;
    const int lane = tid & 31;
    const int g = lane >> 2;
    const int c = lane & 3;

    const int b = blockIdx.y >> 4;
    const int h = blockIdx.y & 15;
    const int row0 = blockIdx.x * 64;
    const int rA = wid * 16 + g;          // warp-local Q row (and rA+8)

    // ---- load Q tile (tf32-converted)
    {
        const size_t qbase = ((size_t)(b * TT + row0)) * EE + h * HDD;
#pragma unroll
        for (int it = 0; it < 8; it++) {
            const int idx = tid + it * 128;
            const int r = idx >> 4, dv = idx & 15;
            float4 qv = *(const float4*)(q + qbase + (size_t)r * EE + dv * 4);
            uint4 t = { f2tf32(qv.x), f2tf32(qv.y), f2tf32(qv.z), f2tf32(qv.w) };
            *(uint4*)&Qs[r * AS + dv * 4] = t;
        }
    }

    float m0 = -1e30f, m1 = -1e30f, l0 = 0.0f, l1 = 0.0f;
    float o[8][4];
#pragma unroll
    for (int nt = 0; nt < 8; nt++)
#pragma unroll
        for (int e = 0; e < 4; e++) o[nt][e] = 0.0f;

    const float* mrow0 = mask + (size_t)(row0 + rA) * TT;
    const float* mrow1 = mrow0 + 8 * TT;

    for (int s0 = 0; s0 < TT; s0 += 64) {
        // ---- load K (row-major) and V (transposed + swizzled), tf32 bits
        const size_t kb = ((size_t)(b * TT + s0)) * EE + h * HDD;
#pragma unroll
        for (int it = 0; it < 8; it++) {
            const int idx = tid + it * 128;
            const int s = idx >> 4, dv = idx & 15;
            float4 kv = *(const float4*)(k + kb + (size_t)s * EE + dv * 4);
            uint4 t = { f2tf32(kv.x), f2tf32(kv.y), f2tf32(kv.z), f2tf32(kv.w) };
            *(uint4*)&Ks[s * AS + dv * 4] = t;
            float4 vv = *(const float4*)(v + kb + (size_t)s * EE + dv * 4);
            uint32_t pv[4] = { f2tf32(vv.x), f2tf32(vv.y), f2tf32(vv.z), f2tf32(vv.w) };
#pragma unroll
            for (int j = 0; j < 4; j++) {
                const int d = dv * 4 + j;
                Vt[d * AS + (s ^ (d & 60))] = pv[j];
            }
        }
        __syncthreads();

        // ---- S = Q K^T
        float sc[8][4];
#pragma unroll
        for (int nt = 0; nt < 8; nt++)
#pragma unroll
            for (int e = 0; e < 4; e++) sc[nt][e] = 0.0f;

#pragma unroll
        for (int ks = 0; ks < 8; ks++) {
            const uint32_t a0 = Qs[rA * AS + ks * 8 + c];
            const uint32_t a1 = Qs[(rA + 8) * AS + ks * 8 + c];
            const uint32_t a2 = Qs[rA * AS + ks * 8 + c + 4];
            const uint32_t a3 = Qs[(rA + 8) * AS + ks * 8 + c + 4];
#pragma unroll
            for (int nt = 0; nt < 8; nt++) {
                const uint32_t b0 = Ks[(nt * 8 + g) * AS + ks * 8 + c];
                const uint32_t b1 = Ks[(nt * 8 + g) * AS + ks * 8 + c + 4];
                mma_tf32(sc[nt][0], sc[nt][1], sc[nt][2], sc[nt][3],
                         a0, a1, a2, a3, b0, b1);
            }
        }

        // ---- + mask, row maxima
        float rx0 = -1e30f, rx1 = -1e30f;
#pragma unroll
        for (int nt = 0; nt < 8; nt++) {
            const float2 mv0 = *(const float2*)(mrow0 + s0 + nt * 8 + 2 * c);
            const float2 mv1 = *(const float2*)(mrow1 + s0 + nt * 8 + 2 * c);
            sc[nt][0] += mv0.x; sc[nt][1] += mv0.y;
            sc[nt][2] += mv1.x; sc[nt][3] += mv1.y;
            rx0 = fmaxf(rx0, fmaxf(sc[nt][0], sc[nt][1]));
            rx1 = fmaxf(rx1, fmaxf(sc[nt][2], sc[nt][3]));
        }
        rx0 = fmaxf(rx0, __shfl_xor_sync(0xffffffffu, rx0, 1));
        rx0 = fmaxf(rx0, __shfl_xor_sync(0xffffffffu, rx0, 2));
        rx1 = fmaxf(rx1, __shfl_xor_sync(0xffffffffu, rx1, 1));
        rx1 = fmaxf(rx1, __shfl_xor_sync(0xffffffffu, rx1, 2));

        const float mn0 = fmaxf(m0, rx0);
        const float mn1 = fmaxf(m1, rx1);
        const float co0 = fexp2((m0 - mn0) * LOG2E);
        const float co1 = fexp2((m1 - mn1) * LOG2E);

        float su0 = 0.0f, su1 = 0.0f;
#pragma unroll
        for (int nt = 0; nt < 8; nt++) {
            const float p0 = fexp2((sc[nt][0] - mn0) * LOG2E);
            const float p1 = fexp2((sc[nt][1] - mn0) * LOG2E);
            const float p2 = fexp2((sc[nt][2] - mn1) * LOG2E);
            const float p3 = fexp2((sc[nt][3] - mn1) * LOG2E);
            sc[nt][0] = p0; sc[nt][1] = p1; sc[nt][2] = p2; sc[nt][3] = p3;
            su0 += p0 + p1; su1 += p2 + p3;
        }
        su0 += __shfl_xor_sync(0xffffffffu, su0, 1);
        su0 += __shfl_xor_sync(0xffffffffu, su0, 2);
        su1 += __shfl_xor_sync(0xffffffffu, su1, 1);
        su1 += __shfl_xor_sync(0xffffffffu, su1, 2);

        l0 = l0 * co0 + su0;  m0 = mn0;
        l1 = l1 * co1 + su1;  m1 = mn1;

#pragma unroll
        for (int nt = 0; nt < 8; nt++) {
            o[nt][0] *= co0; o[nt][1] *= co0;
            o[nt][2] *= co1; o[nt][3] *= co1;
        }

        // ---- P -> smem (warp-local rows, tf32 bits)
#pragma unroll
        for (int nt = 0; nt < 8; nt++) {
            uint2 w0 = { f2tf32(sc[nt][0]), f2tf32(sc[nt][1]) };
            uint2 w1 = { f2tf32(sc[nt][2]), f2tf32(sc[nt][3]) };
            *(uint2*)&Ps[rA * AS + nt * 8 + 2 * c] = w0;
            *(uint2*)&Ps[(rA + 8) * AS + nt * 8 + 2 * c] = w1;
        }
        __syncwarp();

        // ---- O += P V
#pragma unroll
        for (int ks = 0; ks < 8; ks++) {
            const uint32_t a0 = Ps[rA * AS + ks * 8 + c];
            const uint32_t a1 = Ps[(rA + 8) * AS + ks * 8 + c];
            const uint32_t a2 = Ps[rA * AS + ks * 8 + c + 4];
            const uint32_t a3 = Ps[(rA + 8) * AS + ks * 8 + c + 4];
#pragma unroll
            for (int nt = 0; nt < 8; nt++) {
                const int d = nt * 8 + g;
                const uint32_t b0 = Vt[d * AS + ((ks * 8 + c) ^ (d & 60))];
                const uint32_t b1 = Vt[d * AS + ((ks * 8 + c + 4) ^ (d & 60))];
                mma_tf32(o[nt][0], o[nt][1], o[nt][2], o[nt][3],
                         a0, a1, a2, a3, b0, b1);
            }
        }
        __syncthreads();
    }

    // ---- write O
    const float inv0 = 1.0f / l0;
    const float inv1 = 1.0f / l1;
    float* orow0 = out + (size_t)(b * TT + row0 + rA) * EE + h * HDD;
    float* orow1 = orow0 + 8 * EE;
#pragma unroll
    for (int nt = 0; nt < 8; nt++) {
        float2 w0 = { o[nt][0] * inv0, o[nt][1] * inv0 };
        float2 w1 = { o[nt][2] * inv1, o[nt][3] * inv1 };
        *(float2*)(orow0 + nt * 8 + 2 * c) = w0;
        *(float2*)(orow1 + nt * 8 + 2 * c) = w1;
    }
}

// ---------------------------------------------------------------------------
// Multiway LayerNorm (unchanged)
// ---------------------------------------------------------------------------
__global__ __launch_bounds__(256) void mw_ln_kernel(
    const float* __restrict__ x,
    const float* __restrict__ gt, const float* __restrict__ bt,
    const float* __restrict__ gi, const float* __restrict__ bi,
    float* __restrict__ y, const int* __restrict__ split_ptr)
{
    __shared__ float red[8];
    const int row = blockIdx.x;
    const int split = *split_ptr;
    const bool is_text = (row % TT) < split;
    const float* __restrict__ g = is_text ? gt : gi;
    const float* __restrict__ bb = is_text ? bt : bi;

    const int tid = threadIdx.x;
    const float4 v = *(const float4*)(x + (size_t)row * EE + tid * 4);

    float s = v.x + v.y + v.z + v.w;
#pragma unroll
    for (int off = 16; off; off >>= 1) s += __shfl_xor_sync(0xffffffffu, s, off);
    if ((tid & 31) == 0) red[tid >> 5] = s;
    __syncthreads();
    float tot = 0.0f;
    if (tid < 8) tot = red[tid];
    if (tid < 8) {
#pragma unroll
        for (int off = 4; off; off >>= 1) tot += __shfl_xor_sync(0xffu, tot, off);
        if (tid == 0) red[0] = tot;
    }
    __syncthreads();
    const float mean = red[0] * (1.0f / EE);
    __syncthreads();

    const float d0 = v.x - mean, d1 = v.y - mean, d2 = v.z - mean, d3 = v.w - mean;
    float sq = d0*d0 + d1*d1 + d2*d2 + d3*d3;
#pragma unroll
    for (int off = 16; off; off >>= 1) sq += __shfl_xor_sync(0xffffffffu, sq, off);
    if ((tid & 31) == 0) red[tid >> 5] = sq;
    __syncthreads();
    float sqt = 0.0f;
    if (tid < 8) sqt = red[tid];
    if (tid < 8) {
#pragma unroll
        for (int off = 4; off; off >>= 1) sqt += __shfl_xor_sync(0xffu, sqt, off);
        if (tid == 0) red[0] = sqt;
    }
    __syncthreads();
    const float var = red[0] * (1.0f / EE);
    const float rstd = rsqrtf(var + 1e-5f);

    const float4 gv = *(const float4*)(g + tid * 4);
    const float4 bv = *(const float4*)(bb + tid * 4);
    float4 o;
    o.x = d0 * rstd * gv.x + bv.x;
    o.y = d1 * rstd * gv.y + bv.y;
    o.z = d2 * rstd * gv.z + bv.z;
    o.w = d3 * rstd * gv.w + bv.w;
    *(float4*)(y + (size_t)row * EE + tid * 4) = o;
}

// ---------------------------------------------------------------------------
// Launch
// ---------------------------------------------------------------------------
extern "C" void kernel_launch(void* const* d_in, const int* in_sizes, int n_in,
                              void* d_out, int out_size)
{
    const float* query = (const float*)d_in[0];
    const float* key   = (const float*)d_in[1];
    const float* value = (const float*)d_in[2];
    const float* mask  = (const float*)d_in[3];
    const float* Wq_t = (const float*)d_in[4];   const float* bq_t = (const float*)d_in[5];
    const float* Wq_i = (const float*)d_in[6];   const float* bq_i = (const float*)d_in[7];
    const float* Wk_t = (const float*)d_in[8];   const float* bk_t = (const float*)d_in[9];
    const float* Wk_i = (const float*)d_in[10];  const float* bk_i = (const float*)d_in[11];
    const float* Wv_t = (const float*)d_in[12];  const float* bv_t = (const float*)d_in[13];
    const float* Wv_i = (const float*)d_in[14];  const float* bv_i = (const float*)d_in[15];
    const float* Wo_t = (const float*)d_in[16];  const float* bo_t = (const float*)d_in[17];
    const float* Wo_i = (const float*)d_in[18];  const float* bo_i = (const float*)d_in[19];
    const float* ln_g_t = (const float*)d_in[20]; const float* ln_b_t = (const float*)d_in[21];
    const float* ln_g_i = (const float*)d_in[22]; const float* ln_b_i = (const float*)d_in[23];
    const int*   split  = (const int*)d_in[24];

    float *qp, *kp, *vp, *ap;
    cudaGetSymbolAddress((void**)&qp, g_q);
    cudaGetSymbolAddress((void**)&kp, g_k);
    cudaGetSymbolAddress((void**)&vp, g_v);
    cudaGetSymbolAddress((void**)&ap, g_attn);

    const dim3 ggrid(EE / 128, MM / 128);   // (8, 64)
    const float scaling = 0.125f;           // HD^-0.5, HD=64

    cudaFuncSetAttribute(mw_gemm_mma,
                         cudaFuncAttributeMaxDynamicSharedMemorySize, GEMM_SMEM);

    mw_gemm_mma<<<ggrid, 256, GEMM_SMEM>>>(query, Wq_t, bq_t, Wq_i, bq_i, qp, scaling, split);
    mw_gemm_mma<<<ggrid, 256, GEMM_SMEM>>>(key,   Wk_t, bk_t, Wk_i, bk_i, kp, 1.0f,    split);
    mw_gemm_mma<<<ggrid, 256, GEMM_SMEM>>>(value, Wv_t, bv_t, Wv_i, bv_i, vp, 1.0f,    split);

    cudaFuncSetAttribute(attention_mma,
                         cudaFuncAttributeMaxDynamicSharedMemorySize, ATTN_SMEM);
    attention_mma<<<dim3(TT / 64, BB * HH), 128, ATTN_SMEM>>>(qp, kp, vp, mask, ap);

    mw_ln_kernel<<<MM, 256>>>(ap, ln_g_t, ln_b_t, ln_g_i, ln_b_i, qp, split);

    mw_gemm_mma<<<ggrid, 256, GEMM_SMEM>>>(qp, Wo_t, bo_t, Wo_i, bo_i, (float*)d_out, 1.0f, split);
}